// round 5
// baseline (speedup 1.0000x reference)
#include <cuda_runtime.h>
#include <cuda_bf16.h>
#include <math.h>
#include <stdint.h>

#define B_Q    1024
#define NCORP  262144
#define KDIM   256
#define DMODEL 1024
#define TOPK   8
#define NCAND  32

#define TM      128
#define TN      128
#define NCHUNKS 128
#define CHUNK   2048
#define NTILES  16
#define QTILES  8
#define NSLABS_TOTAL (NTILES * 4)    // 64 x 64-K slabs per CTA

// byte pitches (odd 16B-unit counts -> conflict-free ldsm)
#define LDA_B  528      // A: 512B data + 16B pad
#define LDB_B  144      // B slab: 128B data + 16B pad
#define LDS_B  272      // staging: 256B data + 16B pad

#define SM_A     0
#define A_BYTES  (128 * LDA_B)              // 67584
#define SM_B     A_BYTES
#define SB_BYTES (128 * LDB_B)              // 18432 per ring stage
#define SM_S     (SM_B + 4 * SB_BYTES)      // 141312
#define SS_BYTES (128 * LDS_B)              // 34816 per staging buffer
#define SMEM_TOTAL (SM_S + 2 * SS_BYTES)    // 210944

// ---- device-global scratch ----
__device__ __nv_bfloat16 g_qbf[B_Q * KDIM];
__device__ float         g_qn[B_Q * KDIM];
__device__ __nv_bfloat16 g_keysN[(size_t)NCORP * KDIM];     // 128 MB
__device__ float         g_pscore[B_Q * NCHUNKS * TOPK];
__device__ int           g_pidx[B_Q * NCHUNKS * TOPK];
__device__ int           g_cand[B_Q * NCAND];
__device__ int           g_topidx[B_Q * TOPK];

__device__ __forceinline__ bool better(float s1, int i1, float s2, int i2) {
    return (s1 > s2) || (s1 == s2 && i1 < i2);
}
__device__ __forceinline__ uint32_t smem_u32(const void* p) {
    return (uint32_t)__cvta_generic_to_shared(p);
}
__device__ __forceinline__ void ldsm_x4(unsigned* r, unsigned addr) {
    asm volatile("ldmatrix.sync.aligned.m8n8.x4.shared.b16 {%0,%1,%2,%3}, [%4];\n"
        : "=r"(r[0]), "=r"(r[1]), "=r"(r[2]), "=r"(r[3]) : "r"(addr));
}
__device__ __forceinline__ void mma16816(float* d, const unsigned* a, const unsigned* b) {
    asm volatile(
        "mma.sync.aligned.m16n8k16.row.col.f32.bf16.bf16.f32 "
        "{%0,%1,%2,%3}, {%4,%5,%6,%7}, {%8,%9}, {%0,%1,%2,%3};\n"
        : "+f"(d[0]), "+f"(d[1]), "+f"(d[2]), "+f"(d[3])
        : "r"(a[0]), "r"(a[1]), "r"(a[2]), "r"(a[3]), "r"(b[0]), "r"(b[1]));
}
#define CP_ASYNC16(dst, src) \
    asm volatile("cp.async.cg.shared.global [%0], [%1], 16;" :: "r"(dst), "l"(src))
#define CP_COMMIT() asm volatile("cp.async.commit_group;" ::: "memory")
#define CP_WAIT2()  asm volatile("cp.async.wait_group 2;" ::: "memory")

__device__ __forceinline__ void ins8(float ts[8], int ti[8], float v, int idx) {
    ts[7] = v; ti[7] = idx;
#pragma unroll
    for (int j = 7; j > 0; j--) {
        if (ts[j] > ts[j - 1]) {
            float tf = ts[j]; ts[j] = ts[j - 1]; ts[j - 1] = tf;
            int   tt = ti[j]; ti[j] = ti[j - 1]; ti[j - 1] = tt;
        }
    }
}

// ---- kernel 1: normalize queries -> fp32 + bf16 ----
__global__ void qnorm_kernel(const float* __restrict__ q) {
    int row  = (blockIdx.x * blockDim.x + threadIdx.x) >> 5;
    int lane = threadIdx.x & 31;
    if (row >= B_Q) return;
    float x[8];
    *(float4*)&x[0] = *(const float4*)(q + row * KDIM + lane * 8);
    *(float4*)&x[4] = *(const float4*)(q + row * KDIM + lane * 8 + 4);
    float ss = 0.f;
#pragma unroll
    for (int e = 0; e < 8; e++) ss += x[e] * x[e];
#pragma unroll
    for (int o = 16; o > 0; o >>= 1) ss += __shfl_xor_sync(0xffffffffu, ss, o);
    float rinv = 1.0f / fmaxf(sqrtf(ss), 1e-12f);
    __nv_bfloat16 ob[8];
#pragma unroll
    for (int e = 0; e < 8; e++) {
        float v = x[e] * rinv;
        g_qn[row * KDIM + lane * 8 + e] = v;
        ob[e] = __float2bfloat16(v);
    }
    *(uint4*)(g_qbf + row * KDIM + lane * 8) = *(uint4*)ob;
}

// ---- kernel 2: normalize keys -> bf16 row-major ----
__global__ void keysprep_kernel(const float* __restrict__ keys) {
    int row  = (blockIdx.x * blockDim.x + threadIdx.x) >> 5;
    int lane = threadIdx.x & 31;
    if (row >= NCORP) return;
    float x[8];
    *(float4*)&x[0] = *(const float4*)(keys + (size_t)row * KDIM + lane * 8);
    *(float4*)&x[4] = *(const float4*)(keys + (size_t)row * KDIM + lane * 8 + 4);
    float ss = 0.f;
#pragma unroll
    for (int e = 0; e < 8; e++) ss += x[e] * x[e];
#pragma unroll
    for (int o = 16; o > 0; o >>= 1) ss += __shfl_xor_sync(0xffffffffu, ss, o);
    float rinv = 1.0f / fmaxf(sqrtf(ss), 1e-12f);
    __nv_bfloat16 ob[8];
#pragma unroll
    for (int e = 0; e < 8; e++) ob[e] = __float2bfloat16(x[e] * rinv);
    *(uint4*)(g_keysN + (size_t)row * KDIM + lane * 8) = *(uint4*)ob;
}

// ---- kernel 3: 512-thread mma.sync GEMM, 4-stage ring, overlapped scan ----
__global__ __launch_bounds__(512, 1) void score_kernel() {
    extern __shared__ char smem[];
    char* sA = smem + SM_A;
    char* sB = smem + SM_B;
    char* sS = smem + SM_S;

    const int t = threadIdx.x, lane = t & 31, wid = t >> 5;
    const int wm = wid >> 2, wn = wid & 3;          // 4x4 warp grid, 32x32 tiles
    const int q0 = blockIdx.x * TM;
    const int c0 = blockIdx.y * CHUNK;

    // A resident fill
#pragma unroll
    for (int i = 0; i < 8; i++) {
        int u = i * 512 + t; int row = u >> 5, seg = u & 31;
        uint4 v = *(const uint4*)(g_qbf + (size_t)(q0 + row) * KDIM + seg * 8);
        *(uint4*)(sA + row * LDA_B + seg * 16) = v;
    }

    // ldsm base addresses
    unsigned aAddr[2];
    {
        int r = lane & 15, c8 = lane >> 4;
#pragma unroll
        for (int mi = 0; mi < 2; mi++)
            aAddr[mi] = smem_u32(sA + (wm * 32 + mi * 16 + r) * LDA_B + c8 * 16);
    }
    unsigned bRow[2];   // row part within a ring stage
    {
        int bn = (lane & 7) + ((lane >> 4) << 3);
        int bk = ((lane >> 3) & 1) * 16;
#pragma unroll
        for (int np = 0; np < 2; np++)
            bRow[np] = (unsigned)((wn * 32 + np * 16 + bn) * LDB_B + bk);
    }
    const unsigned sbB = smem_u32(sB);

    // scan state: thread owns query (t>>2), quarter (t&3)
    const int qown = t >> 2, qtr = t & 3;
    float ts[8]; int ti[8];
#pragma unroll
    for (int j = 0; j < 8; j++) { ts[j] = -INFINITY; ti[j] = 0x7fffffff; }

    // cp.async: 64-K slab gs -> ring stage gs&3
    auto issue_B = [&](int gs) {
        const int nt = gs >> 2, s4 = gs & 3;
        const __nv_bfloat16* src = g_keysN + (size_t)(c0 + nt * TN) * KDIM + s4 * 64;
        char* dst = sB + (gs & 3) * SB_BYTES;
#pragma unroll
        for (int i = 0; i < 2; i++) {
            int u = i * 512 + t; int row = u >> 3, seg = u & 7;
            CP_ASYNC16(smem_u32(dst + row * LDB_B + seg * 16),
                       (const void*)(src + (size_t)row * KDIM + seg * 8));
        }
    };

    // scan tile nt from staging buffer p
    auto scan_tile = [&](int nt, int p) {
        const int cbase = c0 + nt * TN + qtr * 32;
        const uint4* pp = (const uint4*)(sS + p * SS_BYTES + qown * LDS_B + qtr * 64);
#pragma unroll
        for (int g = 0; g < 4; g++) {
            uint4 v = pp[g];
            __nv_bfloat162 x0 = *(__nv_bfloat162*)&v.x;
            __nv_bfloat162 x1 = *(__nv_bfloat162*)&v.y;
            __nv_bfloat162 x2 = *(__nv_bfloat162*)&v.z;
            __nv_bfloat162 x3 = *(__nv_bfloat162*)&v.w;
            __nv_bfloat162 m = __hmax2(__hmax2(x0, x1), __hmax2(x2, x3));
            float gm = fmaxf(__bfloat162float(m.x), __bfloat162float(m.y));
            if (gm > ts[7]) {
                int b8 = cbase + g * 8;
                float e0 = __bfloat162float(x0.x), e1 = __bfloat162float(x0.y);
                float e2 = __bfloat162float(x1.x), e3 = __bfloat162float(x1.y);
                float e4 = __bfloat162float(x2.x), e5 = __bfloat162float(x2.y);
                float e6 = __bfloat162float(x3.x), e7 = __bfloat162float(x3.y);
                if (e0 > ts[7]) ins8(ts, ti, e0, b8 + 0);
                if (e1 > ts[7]) ins8(ts, ti, e1, b8 + 1);
                if (e2 > ts[7]) ins8(ts, ti, e2, b8 + 2);
                if (e3 > ts[7]) ins8(ts, ti, e3, b8 + 3);
                if (e4 > ts[7]) ins8(ts, ti, e4, b8 + 4);
                if (e5 > ts[7]) ins8(ts, ti, e5, b8 + 5);
                if (e6 > ts[7]) ins8(ts, ti, e6, b8 + 6);
                if (e7 > ts[7]) ins8(ts, ti, e7, b8 + 7);
            }
        }
    };

    float acc[2][4][4];

    issue_B(0); CP_COMMIT();
    issue_B(1); CP_COMMIT();
    issue_B(2); CP_COMMIT();

    for (int gs = 0; gs < NSLABS_TOTAL; gs++) {
        const int s4 = gs & 3, nt = gs >> 2, buf = gs & 3;
        CP_WAIT2();
        __syncthreads();
        if (gs + 3 < NSLABS_TOTAL) issue_B(gs + 3);
        CP_COMMIT();                        // always commit: keeps group count exact

        if (s4 == 0) {
#pragma unroll
            for (int mi = 0; mi < 2; mi++)
#pragma unroll
                for (int nf = 0; nf < 4; nf++)
#pragma unroll
                    for (int e = 0; e < 4; e++) acc[mi][nf][e] = 0.f;
        }

        // 4 k16 steps over this 64-K slab
        const unsigned bStage = sbB + buf * SB_BYTES;
#pragma unroll
        for (int kk = 0; kk < 4; kk++) {
            unsigned af[2][4], bf[2][4];
            const int aofs = s4 * 128 + kk * 32;
            const int bofs = kk * 32;
#pragma unroll
            for (int mi = 0; mi < 2; mi++) ldsm_x4(af[mi], aAddr[mi] + aofs);
#pragma unroll
            for (int np = 0; np < 2; np++) ldsm_x4(bf[np], bStage + bRow[np] + bofs);
#pragma unroll
            for (int mi = 0; mi < 2; mi++) {
#pragma unroll
                for (int np = 0; np < 2; np++) {
                    mma16816(acc[mi][np * 2 + 0], af[mi], &bf[np][0]);
                    mma16816(acc[mi][np * 2 + 1], af[mi], &bf[np][2]);
                }
            }
        }

        // overlapped scan of previous tile (hidden under this tile's mma+loads)
        if (s4 == 0 && nt > 0) scan_tile(nt - 1, (nt - 1) & 1);

        if (s4 == 3) {
            // stage tile scores as bf16 into buffer nt&1
            char* stg = sS + (nt & 1) * SS_BYTES;
#pragma unroll
            for (int mi = 0; mi < 2; mi++) {
#pragma unroll
                for (int nf = 0; nf < 4; nf++) {
                    int r0 = wm * 32 + mi * 16 + (lane >> 2);
                    int cc = wn * 32 + nf * 8 + (lane & 3) * 2;
                    *(__nv_bfloat162*)(stg + r0 * LDS_B + cc * 2) =
                        __floats2bfloat162_rn(acc[mi][nf][0], acc[mi][nf][1]);
                    *(__nv_bfloat162*)(stg + (r0 + 8) * LDS_B + cc * 2) =
                        __floats2bfloat162_rn(acc[mi][nf][2], acc[mi][nf][3]);
                }
            }
        }
    }
    __syncthreads();
    scan_tile(NTILES - 1, (NTILES - 1) & 1);

    // CTA merge: 4 depth-8 lists per query -> chunk top-8
    __syncthreads();
    float* mv = (float*)sS;
    int*   mi2 = (int*)(mv + 512 * 8);
#pragma unroll
    for (int j = 0; j < 8; j++) {
        mv[t * 8 + j] = ts[j]; mi2[t * 8 + j] = ti[j];
    }
    __syncthreads();
    if (t < 128) {
        int p[4] = {0, 0, 0, 0};
        const int Lb = t * 4;
        size_t base = ((size_t)(q0 + t) * NCHUNKS + blockIdx.y) * TOPK;
#pragma unroll
        for (int j = 0; j < TOPK; j++) {
            float bv = -INFINITY; int bi = 0x7fffffff, bl = 0;
#pragma unroll
            for (int l = 0; l < 4; l++) {
                float v = mv[(Lb + l) * 8 + p[l]];
                int   id = mi2[(Lb + l) * 8 + p[l]];
                if (better(v, id, bv, bi)) { bv = v; bi = id; bl = l; }
            }
            p[bl]++;
            g_pscore[base + j] = bv;
            g_pidx[base + j]   = bi;
        }
    }
}

// ---- kernel 4: warp-per-query prune -> approx top-32 ----
__global__ __launch_bounds__(256) void prune_kernel() {
    const int wid = threadIdx.x >> 5, lane = threadIdx.x & 31;
    const int q = blockIdx.x * 8 + wid;
    const float* ps = g_pscore + (size_t)q * NCHUNKS * TOPK;
    const int*   pi = g_pidx   + (size_t)q * NCHUNKS * TOPK;

    float ts[8]; int ti[8];
#pragma unroll
    for (int j = 0; j < 8; j++) { ts[j] = -INFINITY; ti[j] = 0x7fffffff; }
#pragma unroll 4
    for (int pass = 0; pass < 32; pass++) {
        int e = pass * 32 + lane;
        float v = ps[e];
        if (v > ts[7]) ins8(ts, ti, v, pi[e]);
    }
    int p = 0;
    for (int r = 0; r < NCAND; r++) {
        float v = (p < 8) ? ts[p] : -INFINITY;
        int   id = (p < 8) ? ti[p] : 0x7fffffff;
        float bv = v; int bi = id; int bs = lane;
#pragma unroll
        for (int o = 16; o > 0; o >>= 1) {
            float ov = __shfl_xor_sync(0xffffffffu, bv, o);
            int   oi = __shfl_xor_sync(0xffffffffu, bi, o);
            int   os = __shfl_xor_sync(0xffffffffu, bs, o);
            if (ov > bv || (ov == bv && oi < bi)) { bv = ov; bi = oi; bs = os; }
        }
        if (lane == bs) p++;
        if (lane == 0) g_cand[q * NCAND + r] = bi;
    }
}

// ---- kernel 5: exact fp32 rescore + final top-8 ----
__global__ __launch_bounds__(256) void rescore_kernel(const float* __restrict__ keys,
                                                      float* __restrict__ out_scores) {
    __shared__ float cs[NCAND];
    __shared__ int   ci[NCAND];
    int q = blockIdx.x;
    int wid = threadIdx.x >> 5, lane = threadIdx.x & 31;

    float qv[8];
    *(float4*)&qv[0] = *(const float4*)(g_qn + q * KDIM + lane * 8);
    *(float4*)&qv[4] = *(const float4*)(g_qn + q * KDIM + lane * 8 + 4);

    for (int c = wid; c < NCAND; c += 8) {
        int idx = g_cand[q * NCAND + c];
        float kv[8];
        *(float4*)&kv[0] = *(const float4*)(keys + (size_t)idx * KDIM + lane * 8);
        *(float4*)&kv[4] = *(const float4*)(keys + (size_t)idx * KDIM + lane * 8 + 4);
        float ss = 0.f, dt = 0.f;
#pragma unroll
        for (int e = 0; e < 8; e++) { ss += kv[e] * kv[e]; dt += kv[e] * qv[e]; }
#pragma unroll
        for (int o = 16; o > 0; o >>= 1) {
            ss += __shfl_xor_sync(0xffffffffu, ss, o);
            dt += __shfl_xor_sync(0xffffffffu, dt, o);
        }
        if (lane == 0) {
            cs[c] = dt / fmaxf(sqrtf(ss), 1e-12f);
            ci[c] = idx;
        }
    }
    __syncthreads();
    if (threadIdx.x == 0) {
        float ts[TOPK]; int ti[TOPK];
#pragma unroll
        for (int j = 0; j < TOPK; j++) { ts[j] = -INFINITY; ti[j] = 0x7fffffff; }
        for (int c = 0; c < NCAND; c++) {
            float v = cs[c]; int id = ci[c];
            if (better(v, id, ts[TOPK - 1], ti[TOPK - 1])) {
                ts[TOPK - 1] = v; ti[TOPK - 1] = id;
#pragma unroll
                for (int j = TOPK - 1; j > 0; j--) {
                    if (better(ts[j], ti[j], ts[j - 1], ti[j - 1])) {
                        float tf = ts[j]; ts[j] = ts[j - 1]; ts[j - 1] = tf;
                        int   tt = ti[j]; ti[j] = ti[j - 1]; ti[j - 1] = tt;
                    }
                }
            }
        }
#pragma unroll
        for (int j = 0; j < TOPK; j++) {
            out_scores[q * TOPK + j] = ts[j];
            g_topidx[q * TOPK + j]   = ti[j];
        }
    }
}

// ---- kernel 6: gather docs ----
__global__ void gather_kernel(const float* __restrict__ vals, float* __restrict__ out_docs) {
    int b = blockIdx.x;
    int idx = g_topidx[b];
    const float4* src = (const float4*)(vals + (size_t)idx * DMODEL);
    float4* dst = (float4*)(out_docs + (size_t)b * DMODEL);
    dst[threadIdx.x] = src[threadIdx.x];
}

extern "C" void kernel_launch(void* const* d_in, const int* in_sizes, int n_in,
                              void* d_out, int out_size) {
    const float* query = (const float*)d_in[0];
    const float* keys  = (const float*)d_in[1];
    const float* vals  = (const float*)d_in[2];
    float* out        = (float*)d_out;
    float* out_docs   = out;
    float* out_scores = out + (size_t)B_Q * TOPK * DMODEL;

    qnorm_kernel<<<B_Q / 8, 256>>>(query);
    keysprep_kernel<<<NCORP / 8, 256>>>(keys);

    cudaFuncSetAttribute(score_kernel,
                         cudaFuncAttributeMaxDynamicSharedMemorySize, SMEM_TOTAL);
    score_kernel<<<dim3(QTILES, NCHUNKS), 512, SMEM_TOTAL>>>();

    prune_kernel<<<B_Q / 8, 256>>>();
    rescore_kernel<<<B_Q, 256>>>(keys, out_scores);
    gather_kernel<<<B_Q * TOPK, 256>>>(vals, out_docs);
}

// round 9
// speedup vs baseline: 1.0600x; 1.0600x over previous
#include <cuda_runtime.h>
#include <cuda_bf16.h>
#include <math.h>
#include <stdint.h>

#define B_Q    1024
#define NCORP  262144
#define KDIM   256
#define DMODEL 1024
#define TOPK   8
#define NCAND  32

#define TM      64
#define TN      128
#define NCHUNKS 128
#define CHUNK   2048
#define NTILES  16
#define QTILES  (B_Q / TM)           // 16
#define NSLABS_TOTAL (NTILES * 2)    // 32 x 128-K slabs per CTA

// swizzled, pad-free layouts (XOR (row&7) on 16B-unit index)
#define SM_A     0
#define A_BYTES  (64 * 512)                 // 32768
#define SM_B     A_BYTES
#define SB_BYTES (128 * 256)                // 32768 per buffer
#define SM_S     (SM_B + 2 * SB_BYTES)      // 98304
#define SS_BYTES (64 * 256)                 // 16384 staging (pitch 256B)
#define SMEM_TOTAL (SM_S + SS_BYTES)        // 114688  -> 2 CTAs/SM

// ---- device-global scratch ----
__device__ __nv_bfloat16 g_qbf[B_Q * KDIM];
__device__ float         g_qn[B_Q * KDIM];
__device__ __nv_bfloat16 g_keysN[(size_t)NCORP * KDIM];     // 128 MB
__device__ float         g_pscore[B_Q * NCHUNKS * TOPK];
__device__ int           g_pidx[B_Q * NCHUNKS * TOPK];
__device__ int           g_cand[B_Q * NCAND];
__device__ int           g_topidx[B_Q * TOPK];

__device__ __forceinline__ bool better(float s1, int i1, float s2, int i2) {
    return (s1 > s2) || (s1 == s2 && i1 < i2);
}
__device__ __forceinline__ uint32_t smem_u32(const void* p) {
    return (uint32_t)__cvta_generic_to_shared(p);
}
__device__ __forceinline__ void ldsm_x4(unsigned* r, unsigned addr) {
    asm volatile("ldmatrix.sync.aligned.m8n8.x4.shared.b16 {%0,%1,%2,%3}, [%4];\n"
        : "=r"(r[0]), "=r"(r[1]), "=r"(r[2]), "=r"(r[3]) : "r"(addr));
}
__device__ __forceinline__ void mma16816(float* d, const unsigned* a, const unsigned* b) {
    asm volatile(
        "mma.sync.aligned.m16n8k16.row.col.f32.bf16.bf16.f32 "
        "{%0,%1,%2,%3}, {%4,%5,%6,%7}, {%8,%9}, {%0,%1,%2,%3};\n"
        : "+f"(d[0]), "+f"(d[1]), "+f"(d[2]), "+f"(d[3])
        : "r"(a[0]), "r"(a[1]), "r"(a[2]), "r"(a[3]), "r"(b[0]), "r"(b[1]));
}
#define CP_ASYNC16(dst, src) \
    asm volatile("cp.async.cg.shared.global [%0], [%1], 16;" :: "r"(dst), "l"(src))
#define CP_COMMIT() asm volatile("cp.async.commit_group;" ::: "memory")
#define CP_WAIT1()  asm volatile("cp.async.wait_group 1;" ::: "memory")
#define CP_WAIT0()  asm volatile("cp.async.wait_group 0;" ::: "memory")

__device__ __forceinline__ void ins8(float ts[8], int ti[8], float v, int idx) {
    ts[7] = v; ti[7] = idx;
#pragma unroll
    for (int j = 7; j > 0; j--) {
        if (ts[j] > ts[j - 1]) {
            float tf = ts[j]; ts[j] = ts[j - 1]; ts[j - 1] = tf;
            int   tt = ti[j]; ti[j] = ti[j - 1]; ti[j - 1] = tt;
        }
    }
}

// ---- kernel 1: normalize queries -> fp32 + bf16 ----
__global__ void qnorm_kernel(const float* __restrict__ q) {
    int row  = (blockIdx.x * blockDim.x + threadIdx.x) >> 5;
    int lane = threadIdx.x & 31;
    if (row >= B_Q) return;
    float x[8];
    *(float4*)&x[0] = *(const float4*)(q + row * KDIM + lane * 8);
    *(float4*)&x[4] = *(const float4*)(q + row * KDIM + lane * 8 + 4);
    float ss = 0.f;
#pragma unroll
    for (int e = 0; e < 8; e++) ss += x[e] * x[e];
#pragma unroll
    for (int o = 16; o > 0; o >>= 1) ss += __shfl_xor_sync(0xffffffffu, ss, o);
    float rinv = 1.0f / fmaxf(sqrtf(ss), 1e-12f);
    __nv_bfloat16 ob[8];
#pragma unroll
    for (int e = 0; e < 8; e++) {
        float v = x[e] * rinv;
        g_qn[row * KDIM + lane * 8 + e] = v;
        ob[e] = __float2bfloat16(v);
    }
    *(uint4*)(g_qbf + row * KDIM + lane * 8) = *(uint4*)ob;
}

// ---- kernel 2: normalize keys -> bf16 row-major ----
__global__ void keysprep_kernel(const float* __restrict__ keys) {
    int row  = (blockIdx.x * blockDim.x + threadIdx.x) >> 5;
    int lane = threadIdx.x & 31;
    if (row >= NCORP) return;
    float x[8];
    *(float4*)&x[0] = *(const float4*)(keys + (size_t)row * KDIM + lane * 8);
    *(float4*)&x[4] = *(const float4*)(keys + (size_t)row * KDIM + lane * 8 + 4);
    float ss = 0.f;
#pragma unroll
    for (int e = 0; e < 8; e++) ss += x[e] * x[e];
#pragma unroll
    for (int o = 16; o > 0; o >>= 1) ss += __shfl_xor_sync(0xffffffffu, ss, o);
    float rinv = 1.0f / fmaxf(sqrtf(ss), 1e-12f);
    __nv_bfloat16 ob[8];
#pragma unroll
    for (int e = 0; e < 8; e++) ob[e] = __float2bfloat16(x[e] * rinv);
    *(uint4*)(g_keysN + (size_t)row * KDIM + lane * 8) = *(uint4*)ob;
}

// ---- kernel 3: TM=64 mma.sync GEMM, swizzled smem, 2 CTAs/SM ----
__global__ __launch_bounds__(256, 2) void score_kernel() {
    extern __shared__ char smem[];
    char* sA = smem + SM_A;
    char* sS = smem + SM_S;

    const int t = threadIdx.x, lane = t & 31, wid = t >> 5;
    const int wm = wid >> 2, wn = wid & 3;          // 2x4 warp grid, 32x32 tiles
    const int q0 = blockIdx.x * TM;
    const int c0 = blockIdx.y * CHUNK;

    // A resident fill: 64 rows x 512B, swizzled
#pragma unroll
    for (int i = 0; i < 8; i++) {
        int u = i * 256 + t; int row = u >> 5, seg = u & 31;
        uint4 v = *(const uint4*)(g_qbf + (size_t)(q0 + row) * KDIM + seg * 8);
        *(uint4*)(sA + row * 512 + ((seg ^ (row & 7)) * 16)) = v;
    }

    // fragment address components (row&7 == lane&7 for both A and B)
    const unsigned xmask = (unsigned)((lane & 7) * 16);
    unsigned aBase[2];
    {
        int r = lane & 15;
#pragma unroll
        for (int mi = 0; mi < 2; mi++)
            aBase[mi] = smem_u32(sA + (wm * 32 + mi * 16 + r) * 512);
    }
    const unsigned c8off = (unsigned)((lane >> 4) * 16);
    unsigned bRow[2];
    {
        int bn = (lane & 7) + ((lane >> 4) << 3);
#pragma unroll
        for (int np = 0; np < 2; np++)
            bRow[np] = (unsigned)((wn * 32 + np * 16 + bn) * 256);
    }
    const unsigned bhalf = (unsigned)(((lane >> 3) & 1) * 16);
    const unsigned sbB = smem_u32(smem + SM_B);

    // scan state: thread owns query (t>>2), quarter (t&3)
    const int qown = t >> 2, qtr = t & 3;
    float ts[8]; int ti[8];
#pragma unroll
    for (int j = 0; j < 8; j++) { ts[j] = -INFINITY; ti[j] = 0x7fffffff; }

    // cp.async: 128-K slab (tile nt, half s) -> buffer buf, swizzled
    auto issue_B = [&](int gs, int buf) {
        const int nt = gs >> 1, s = gs & 1;
        const __nv_bfloat16* src = g_keysN + (size_t)(c0 + nt * TN) * KDIM + s * 128;
        char* dst = smem + SM_B + buf * SB_BYTES;
#pragma unroll
        for (int i = 0; i < 8; i++) {
            int u = i * 256 + t; int row = u >> 4, seg = u & 15;
            CP_ASYNC16(smem_u32(dst + row * 256 + ((seg ^ (row & 7)) * 16)),
                       (const void*)(src + (size_t)row * KDIM + seg * 8));
        }
    };

    float acc[2][4][4];

    issue_B(0, 0); CP_COMMIT();

    for (int gs = 0; gs < NSLABS_TOTAL; gs++) {
        const int buf = gs & 1, s = gs & 1, nt = gs >> 1;
        if (gs + 1 < NSLABS_TOTAL) { issue_B(gs + 1, buf ^ 1); CP_COMMIT(); CP_WAIT1(); }
        else CP_WAIT0();
        __syncthreads();

        if (s == 0) {
#pragma unroll
            for (int mi = 0; mi < 2; mi++)
#pragma unroll
                for (int nf = 0; nf < 4; nf++)
#pragma unroll
                    for (int e = 0; e < 4; e++) acc[mi][nf][e] = 0.f;
        }

        // 8 k16 steps over this 128-K slab
        const unsigned bStage = sbB + buf * SB_BYTES;
#pragma unroll
        for (int kk = 0; kk < 8; kk++) {
            unsigned af[2][4], bf[2][4];
            const unsigned aofs = (unsigned)(s * 256 + kk * 32) + c8off;
            const unsigned bofs = (unsigned)(kk * 32) + bhalf;
#pragma unroll
            for (int mi = 0; mi < 2; mi++)
                ldsm_x4(af[mi], aBase[mi] + (aofs ^ xmask));
#pragma unroll
            for (int np = 0; np < 2; np++)
                ldsm_x4(bf[np], bStage + bRow[np] + (bofs ^ xmask));
#pragma unroll
            for (int mi = 0; mi < 2; mi++) {
#pragma unroll
                for (int np = 0; np < 2; np++) {
                    mma16816(acc[mi][np * 2 + 0], af[mi], &bf[np][0]);
                    mma16816(acc[mi][np * 2 + 1], af[mi], &bf[np][2]);
                }
            }
        }

        if (s == 1) {
            // stage tile scores to sS as bf16 (pitch 256B)
#pragma unroll
            for (int mi = 0; mi < 2; mi++) {
#pragma unroll
                for (int nf = 0; nf < 4; nf++) {
                    int r0 = wm * 32 + mi * 16 + (lane >> 2);
                    int cc = wn * 32 + nf * 8 + (lane & 3) * 2;
                    *(__nv_bfloat162*)(sS + r0 * 256 + cc * 2) =
                        __floats2bfloat162_rn(acc[mi][nf][0], acc[mi][nf][1]);
                    *(__nv_bfloat162*)(sS + (r0 + 8) * 256 + cc * 2) =
                        __floats2bfloat162_rn(acc[mi][nf][2], acc[mi][nf][3]);
                }
            }
            __syncthreads();
            // scan 32 cols: group-max filter then detail insert
            {
                const int cbase = c0 + nt * TN + qtr * 32;
                const uint4* p = (const uint4*)(sS + qown * 256 + qtr * 64);
#pragma unroll
                for (int g = 0; g < 4; g++) {
                    uint4 v = p[g];
                    __nv_bfloat162 x0 = *(__nv_bfloat162*)&v.x;
                    __nv_bfloat162 x1 = *(__nv_bfloat162*)&v.y;
                    __nv_bfloat162 x2 = *(__nv_bfloat162*)&v.z;
                    __nv_bfloat162 x3 = *(__nv_bfloat162*)&v.w;
                    __nv_bfloat162 m = __hmax2(__hmax2(x0, x1), __hmax2(x2, x3));
                    float gm = fmaxf(__bfloat162float(m.x), __bfloat162float(m.y));
                    if (gm > ts[7]) {
                        int b8 = cbase + g * 8;
                        float e0 = __bfloat162float(x0.x), e1 = __bfloat162float(x0.y);
                        float e2 = __bfloat162float(x1.x), e3 = __bfloat162float(x1.y);
                        float e4 = __bfloat162float(x2.x), e5 = __bfloat162float(x2.y);
                        float e6 = __bfloat162float(x3.x), e7 = __bfloat162float(x3.y);
                        if (e0 > ts[7]) ins8(ts, ti, e0, b8 + 0);
                        if (e1 > ts[7]) ins8(ts, ti, e1, b8 + 1);
                        if (e2 > ts[7]) ins8(ts, ti, e2, b8 + 2);
                        if (e3 > ts[7]) ins8(ts, ti, e3, b8 + 3);
                        if (e4 > ts[7]) ins8(ts, ti, e4, b8 + 4);
                        if (e5 > ts[7]) ins8(ts, ti, e5, b8 + 5);
                        if (e6 > ts[7]) ins8(ts, ti, e6, b8 + 6);
                        if (e7 > ts[7]) ins8(ts, ti, e7, b8 + 7);
                    }
                }
            }
            __syncthreads();
        } else {
            __syncthreads();   // end-of-iteration barrier (protects buffers)
        }
    }

    // CTA merge: 4 depth-8 lists per query -> chunk top-8 (reuses sS: 16KB)
    float* mv = (float*)sS;
    int*   mi2 = (int*)(mv + 256 * 8);
#pragma unroll
    for (int j = 0; j < 8; j++) {
        mv[t * 8 + j] = ts[j]; mi2[t * 8 + j] = ti[j];
    }
    __syncthreads();
    if (t < TM) {
        int p[4] = {0, 0, 0, 0};
        const int Lb = t * 4;
        size_t base = ((size_t)(q0 + t) * NCHUNKS + blockIdx.y) * TOPK;
#pragma unroll
        for (int j = 0; j < TOPK; j++) {
            float bv = -INFINITY; int bi = 0x7fffffff, bl = 0;
#pragma unroll
            for (int l = 0; l < 4; l++) {
                float v = mv[(Lb + l) * 8 + p[l]];
                int   id = mi2[(Lb + l) * 8 + p[l]];
                if (better(v, id, bv, bi)) { bv = v; bi = id; bl = l; }
            }
            p[bl]++;
            g_pscore[base + j] = bv;
            g_pidx[base + j]   = bi;
        }
    }
}

// ---- kernel 4: warp-per-query prune -> approx top-32 ----
__global__ __launch_bounds__(256) void prune_kernel() {
    const int wid = threadIdx.x >> 5, lane = threadIdx.x & 31;
    const int q = blockIdx.x * 8 + wid;
    const float* ps = g_pscore + (size_t)q * NCHUNKS * TOPK;
    const int*   pi = g_pidx   + (size_t)q * NCHUNKS * TOPK;

    float ts[8]; int ti[8];
#pragma unroll
    for (int j = 0; j < 8; j++) { ts[j] = -INFINITY; ti[j] = 0x7fffffff; }
#pragma unroll 4
    for (int pass = 0; pass < 32; pass++) {
        int e = pass * 32 + lane;
        float v = ps[e];
        if (v > ts[7]) ins8(ts, ti, v, pi[e]);
    }
    int p = 0;
    for (int r = 0; r < NCAND; r++) {
        float v = (p < 8) ? ts[p] : -INFINITY;
        int   id = (p < 8) ? ti[p] : 0x7fffffff;
        float bv = v; int bi = id; int bs = lane;
#pragma unroll
        for (int o = 16; o > 0; o >>= 1) {
            float ov = __shfl_xor_sync(0xffffffffu, bv, o);
            int   oi = __shfl_xor_sync(0xffffffffu, bi, o);
            int   os = __shfl_xor_sync(0xffffffffu, bs, o);
            if (ov > bv || (ov == bv && oi < bi)) { bv = ov; bi = oi; bs = os; }
        }
        if (lane == bs) p++;
        if (lane == 0) g_cand[q * NCAND + r] = bi;
    }
}

// ---- kernel 5: exact fp32 rescore + final top-8 ----
__global__ __launch_bounds__(256) void rescore_kernel(const float* __restrict__ keys,
                                                      float* __restrict__ out_scores) {
    __shared__ float cs[NCAND];
    __shared__ int   ci[NCAND];
    int q = blockIdx.x;
    int wid = threadIdx.x >> 5, lane = threadIdx.x & 31;

    float qv[8];
    *(float4*)&qv[0] = *(const float4*)(g_qn + q * KDIM + lane * 8);
    *(float4*)&qv[4] = *(const float4*)(g_qn + q * KDIM + lane * 8 + 4);

    for (int c = wid; c < NCAND; c += 8) {
        int idx = g_cand[q * NCAND + c];
        float kv[8];
        *(float4*)&kv[0] = *(const float4*)(keys + (size_t)idx * KDIM + lane * 8);
        *(float4*)&kv[4] = *(const float4*)(keys + (size_t)idx * KDIM + lane * 8 + 4);
        float ss = 0.f, dt = 0.f;
#pragma unroll
        for (int e = 0; e < 8; e++) { ss += kv[e] * kv[e]; dt += kv[e] * qv[e]; }
#pragma unroll
        for (int o = 16; o > 0; o >>= 1) {
            ss += __shfl_xor_sync(0xffffffffu, ss, o);
            dt += __shfl_xor_sync(0xffffffffu, dt, o);
        }
        if (lane == 0) {
            cs[c] = dt / fmaxf(sqrtf(ss), 1e-12f);
            ci[c] = idx;
        }
    }
    __syncthreads();
    if (threadIdx.x == 0) {
        float ts[TOPK]; int ti[TOPK];
#pragma unroll
        for (int j = 0; j < TOPK; j++) { ts[j] = -INFINITY; ti[j] = 0x7fffffff; }
        for (int c = 0; c < NCAND; c++) {
            float v = cs[c]; int id = ci[c];
            if (better(v, id, ts[TOPK - 1], ti[TOPK - 1])) {
                ts[TOPK - 1] = v; ti[TOPK - 1] = id;
#pragma unroll
                for (int j = TOPK - 1; j > 0; j--) {
                    if (better(ts[j], ti[j], ts[j - 1], ti[j - 1])) {
                        float tf = ts[j]; ts[j] = ts[j - 1]; ts[j - 1] = tf;
                        int   tt = ti[j]; ti[j] = ti[j - 1]; ti[j - 1] = tt;
                    }
                }
            }
        }
#pragma unroll
        for (int j = 0; j < TOPK; j++) {
            out_scores[q * TOPK + j] = ts[j];
            g_topidx[q * TOPK + j]   = ti[j];
        }
    }
}

// ---- kernel 6: gather docs ----
__global__ void gather_kernel(const float* __restrict__ vals, float* __restrict__ out_docs) {
    int b = blockIdx.x;
    int idx = g_topidx[b];
    const float4* src = (const float4*)(vals + (size_t)idx * DMODEL);
    float4* dst = (float4*)(out_docs + (size_t)b * DMODEL);
    dst[threadIdx.x] = src[threadIdx.x];
}

extern "C" void kernel_launch(void* const* d_in, const int* in_sizes, int n_in,
                              void* d_out, int out_size) {
    const float* query = (const float*)d_in[0];
    const float* keys  = (const float*)d_in[1];
    const float* vals  = (const float*)d_in[2];
    float* out        = (float*)d_out;
    float* out_docs   = out;
    float* out_scores = out + (size_t)B_Q * TOPK * DMODEL;

    qnorm_kernel<<<B_Q / 8, 256>>>(query);
    keysprep_kernel<<<NCORP / 8, 256>>>(keys);

    cudaFuncSetAttribute(score_kernel,
                         cudaFuncAttributeMaxDynamicSharedMemorySize, SMEM_TOTAL);
    score_kernel<<<dim3(QTILES, NCHUNKS), 256, SMEM_TOTAL>>>();

    prune_kernel<<<B_Q / 8, 256>>>();
    rescore_kernel<<<B_Q, 256>>>(keys, out_scores);
    gather_kernel<<<B_Q * TOPK, 256>>>(vals, out_docs);
}

// round 14
// speedup vs baseline: 1.3832x; 1.3048x over previous
#include <cuda_runtime.h>
#include <cuda_bf16.h>
#include <cuda_fp8.h>
#include <math.h>
#include <stdint.h>

#define B_Q    1024
#define NCORP  262144
#define KDIM   256
#define DMODEL 1024
#define TOPK   8
#define NCAND  256
#define PCHUNK 32                    // raw entries per (query, chunk)

#define TM      128
#define TN      128
#define NCHUNKS 128
#define CHUNK   2048
#define NTILES  16
#define QTILES  8
#define NSLABS_TOTAL (NTILES * 2)    // 32 x 128-elem K slabs

// byte pitches (odd 16B-unit counts -> conflict-free ldsm)
#define LDA_B  272      // A fp8: 256B data + 16B pad
#define LDB_B  144      // B fp8 slab: 128B data + 16B pad
#define LDS_B  272      // staging: 256B bf16 data + 16B pad

#define SM_A     0
#define A_BYTES  (128 * LDA_B)              // 34816
#define SM_B     A_BYTES
#define SB_BYTES (128 * LDB_B)              // 18432 per buffer
#define SM_S     (SM_B + 2 * SB_BYTES)      // 71680
#define SS_BYTES (128 * LDS_B)              // 34816
#define SMEM_TOTAL (SM_S + SS_BYTES)        // 106496

// ---- device-global scratch ----
__device__ unsigned char g_qf8[B_Q * KDIM];
__device__ float         g_qn[B_Q * KDIM];
__device__ unsigned char g_keysF8[(size_t)NCORP * KDIM];        // 64 MB
__device__ float         g_pscore[(size_t)B_Q * NCHUNKS * PCHUNK]; // 16 MB
__device__ int           g_pidx[(size_t)B_Q * NCHUNKS * PCHUNK];   // 16 MB
__device__ int           g_cand[B_Q * NCAND];                   // 1 MB
__device__ int           g_topidx[B_Q * TOPK];

__device__ __forceinline__ bool better(float s1, int i1, float s2, int i2) {
    return (s1 > s2) || (s1 == s2 && i1 < i2);
}
__device__ __forceinline__ uint32_t smem_u32(const void* p) {
    return (uint32_t)__cvta_generic_to_shared(p);
}
__device__ __forceinline__ void ldsm_x4(unsigned* r, unsigned addr) {
    asm volatile("ldmatrix.sync.aligned.m8n8.x4.shared.b16 {%0,%1,%2,%3}, [%4];\n"
        : "=r"(r[0]), "=r"(r[1]), "=r"(r[2]), "=r"(r[3]) : "r"(addr));
}
// fp8 e4m3 MMA: m16n8k32, fragments pair-identical to m16n8k16.bf16
__device__ __forceinline__ void mma16832(float* d, const unsigned* a, const unsigned* b) {
    asm volatile(
        "mma.sync.aligned.m16n8k32.row.col.f32.e4m3.e4m3.f32 "
        "{%0,%1,%2,%3}, {%4,%5,%6,%7}, {%8,%9}, {%0,%1,%2,%3};\n"
        : "+f"(d[0]), "+f"(d[1]), "+f"(d[2]), "+f"(d[3])
        : "r"(a[0]), "r"(a[1]), "r"(a[2]), "r"(a[3]), "r"(b[0]), "r"(b[1]));
}
#define CP_ASYNC16(dst, src) \
    asm volatile("cp.async.cg.shared.global [%0], [%1], 16;" :: "r"(dst), "l"(src))
#define CP_COMMIT() asm volatile("cp.async.commit_group;" ::: "memory")
#define CP_WAIT1()  asm volatile("cp.async.wait_group 1;" ::: "memory")
#define CP_WAIT0()  asm volatile("cp.async.wait_group 0;" ::: "memory")

__device__ __forceinline__ void ins8(float ts[8], int ti[8], float v, int idx) {
    ts[7] = v; ti[7] = idx;
#pragma unroll
    for (int j = 7; j > 0; j--) {
        if (ts[j] > ts[j - 1]) {
            float tf = ts[j]; ts[j] = ts[j - 1]; ts[j - 1] = tf;
            int   tt = ti[j]; ti[j] = ti[j - 1]; ti[j - 1] = tt;
        }
    }
}

__device__ __forceinline__ unsigned char to_e4m3(float v) {
    return (unsigned char)__nv_cvt_float_to_fp8(v, __NV_SATFINITE, __NV_E4M3);
}

// ---- kernel 1: normalize queries -> fp32 + fp8 ----
__global__ void qnorm_kernel(const float* __restrict__ q) {
    int row  = (blockIdx.x * blockDim.x + threadIdx.x) >> 5;
    int lane = threadIdx.x & 31;
    if (row >= B_Q) return;
    float x[8];
    *(float4*)&x[0] = *(const float4*)(q + row * KDIM + lane * 8);
    *(float4*)&x[4] = *(const float4*)(q + row * KDIM + lane * 8 + 4);
    float ss = 0.f;
#pragma unroll
    for (int e = 0; e < 8; e++) ss += x[e] * x[e];
#pragma unroll
    for (int o = 16; o > 0; o >>= 1) ss += __shfl_xor_sync(0xffffffffu, ss, o);
    float rinv = 1.0f / fmaxf(sqrtf(ss), 1e-12f);
    unsigned char ob[8];
#pragma unroll
    for (int e = 0; e < 8; e++) {
        float v = x[e] * rinv;
        g_qn[row * KDIM + lane * 8 + e] = v;
        ob[e] = to_e4m3(v);
    }
    *(uint2*)(g_qf8 + row * KDIM + lane * 8) = *(uint2*)ob;
}

// ---- kernel 2: normalize keys -> fp8 row-major ----
__global__ void keysprep_kernel(const float* __restrict__ keys) {
    int row  = (blockIdx.x * blockDim.x + threadIdx.x) >> 5;
    int lane = threadIdx.x & 31;
    if (row >= NCORP) return;
    float x[8];
    *(float4*)&x[0] = *(const float4*)(keys + (size_t)row * KDIM + lane * 8);
    *(float4*)&x[4] = *(const float4*)(keys + (size_t)row * KDIM + lane * 8 + 4);
    float ss = 0.f;
#pragma unroll
    for (int e = 0; e < 8; e++) ss += x[e] * x[e];
#pragma unroll
    for (int o = 16; o > 0; o >>= 1) ss += __shfl_xor_sync(0xffffffffu, ss, o);
    float rinv = 1.0f / fmaxf(sqrtf(ss), 1e-12f);
    unsigned char ob[8];
#pragma unroll
    for (int e = 0; e < 8; e++) ob[e] = to_e4m3(x[e] * rinv);
    *(uint2*)(g_keysF8 + (size_t)row * KDIM + lane * 8) = *(uint2*)ob;
}

// ---- kernel 3: 512-thread fp8 mma GEMM; raw 32-entry per-chunk emission ----
__global__ __launch_bounds__(512, 1) void score_kernel() {
    extern __shared__ char smem[];
    char* sA = smem + SM_A;
    char* sB = smem + SM_B;
    char* sS = smem + SM_S;

    const int t = threadIdx.x, lane = t & 31, wid = t >> 5;
    const int wm = wid >> 2, wn = wid & 3;          // 4x4 warp grid, 32x32 tiles
    const int q0 = blockIdx.x * TM;
    const int c0 = blockIdx.y * CHUNK;

    // A resident fill: 128 rows x 256B fp8
#pragma unroll
    for (int i = 0; i < 4; i++) {
        int u = i * 512 + t; int row = u >> 4, seg = u & 15;
        uint4 v = *(const uint4*)(g_qf8 + (size_t)(q0 + row) * KDIM + seg * 16);
        *(uint4*)(sA + row * LDA_B + seg * 16) = v;
    }

    // ldsm base addresses (pair-view: fp8 k32 frag == b16 k16 frag)
    unsigned aAddr[2];
    {
        int r = lane & 15, c8 = lane >> 4;
#pragma unroll
        for (int mi = 0; mi < 2; mi++)
            aAddr[mi] = smem_u32(sA + (wm * 32 + mi * 16 + r) * LDA_B + c8 * 16);
    }
    unsigned bAddr[2][2];
    {
        int bn = (lane & 7) + ((lane >> 4) << 3);
        int bk = ((lane >> 3) & 1) * 16;
#pragma unroll
        for (int buf = 0; buf < 2; buf++)
#pragma unroll
            for (int np = 0; np < 2; np++)
                bAddr[buf][np] = smem_u32(sB + buf * SB_BYTES +
                                          (wn * 32 + np * 16 + bn) * LDB_B + bk);
    }

    // scan state: thread owns query (t>>2), quarter (t&3)
    const int qown = t >> 2, qtr = t & 3;
    float ts[8]; int ti[8];
#pragma unroll
    for (int j = 0; j < 8; j++) { ts[j] = -INFINITY; ti[j] = 0x7fffffff; }

    // cp.async: slab gs (tile gs>>1, K-half gs&1) -> buffer buf (16KB)
    auto issue_B = [&](int gs, int buf) {
        const int nt = gs >> 1, s = gs & 1;
        const unsigned char* src = g_keysF8 + (size_t)(c0 + nt * TN) * KDIM + s * 128;
        char* dst = sB + buf * SB_BYTES;
#pragma unroll
        for (int i = 0; i < 2; i++) {
            int u = i * 512 + t; int row = u >> 3, seg = u & 7;
            CP_ASYNC16(smem_u32(dst + row * LDB_B + seg * 16),
                       (const void*)(src + (size_t)row * KDIM + seg * 16));
        }
    };

    float acc[2][4][4];

    issue_B(0, 0); CP_COMMIT();

    for (int gs = 0; gs < NSLABS_TOTAL; gs++) {
        const int buf = gs & 1, s = gs & 1, nt = gs >> 1;
        if (gs + 1 < NSLABS_TOTAL) { issue_B(gs + 1, buf ^ 1); CP_COMMIT(); CP_WAIT1(); }
        else CP_WAIT0();
        __syncthreads();

        if (s == 0) {
#pragma unroll
            for (int mi = 0; mi < 2; mi++)
#pragma unroll
                for (int nf = 0; nf < 4; nf++)
#pragma unroll
                    for (int e = 0; e < 4; e++) acc[mi][nf][e] = 0.f;
        }

        // 4 k32 steps over this 128-elem K slab
#pragma unroll
        for (int kk = 0; kk < 4; kk++) {
            unsigned af[2][4], bf[2][4];
            const int aofs = s * 128 + kk * 32;
            const int bofs = kk * 32;
#pragma unroll
            for (int mi = 0; mi < 2; mi++) ldsm_x4(af[mi], aAddr[mi] + aofs);
#pragma unroll
            for (int np = 0; np < 2; np++) ldsm_x4(bf[np], bAddr[buf][np] + bofs);
#pragma unroll
            for (int mi = 0; mi < 2; mi++) {
#pragma unroll
                for (int np = 0; np < 2; np++) {
                    mma16832(acc[mi][np * 2 + 0], af[mi], &bf[np][0]);
                    mma16832(acc[mi][np * 2 + 1], af[mi], &bf[np][2]);
                }
            }
        }

        if (s == 1) {
            // stage tile scores to sS as bf16
#pragma unroll
            for (int mi = 0; mi < 2; mi++) {
#pragma unroll
                for (int nf = 0; nf < 4; nf++) {
                    int r0 = wm * 32 + mi * 16 + (lane >> 2);
                    int cc = wn * 32 + nf * 8 + (lane & 3) * 2;
                    *(__nv_bfloat162*)(sS + r0 * LDS_B + cc * 2) =
                        __floats2bfloat162_rn(acc[mi][nf][0], acc[mi][nf][1]);
                    *(__nv_bfloat162*)(sS + (r0 + 8) * LDS_B + cc * 2) =
                        __floats2bfloat162_rn(acc[mi][nf][2], acc[mi][nf][3]);
                }
            }
            __syncthreads();
            // scan 32 cols: group-max filter then detail insert
            {
                const int cbase = c0 + nt * TN + qtr * 32;
                const uint4* p = (const uint4*)(sS + qown * LDS_B + qtr * 64);
#pragma unroll
                for (int g = 0; g < 4; g++) {
                    uint4 v = p[g];
                    __nv_bfloat162 x0 = *(__nv_bfloat162*)&v.x;
                    __nv_bfloat162 x1 = *(__nv_bfloat162*)&v.y;
                    __nv_bfloat162 x2 = *(__nv_bfloat162*)&v.z;
                    __nv_bfloat162 x3 = *(__nv_bfloat162*)&v.w;
                    __nv_bfloat162 m = __hmax2(__hmax2(x0, x1), __hmax2(x2, x3));
                    float gm = fmaxf(__bfloat162float(m.x), __bfloat162float(m.y));
                    if (gm > ts[7]) {
                        int b8 = cbase + g * 8;
                        float e0 = __bfloat162float(x0.x), e1 = __bfloat162float(x0.y);
                        float e2 = __bfloat162float(x1.x), e3 = __bfloat162float(x1.y);
                        float e4 = __bfloat162float(x2.x), e5 = __bfloat162float(x2.y);
                        float e6 = __bfloat162float(x3.x), e7 = __bfloat162float(x3.y);
                        if (e0 > ts[7]) ins8(ts, ti, e0, b8 + 0);
                        if (e1 > ts[7]) ins8(ts, ti, e1, b8 + 1);
                        if (e2 > ts[7]) ins8(ts, ti, e2, b8 + 2);
                        if (e3 > ts[7]) ins8(ts, ti, e3, b8 + 3);
                        if (e4 > ts[7]) ins8(ts, ti, e4, b8 + 4);
                        if (e5 > ts[7]) ins8(ts, ti, e5, b8 + 5);
                        if (e6 > ts[7]) ins8(ts, ti, e6, b8 + 6);
                        if (e7 > ts[7]) ins8(ts, ti, e7, b8 + 7);
                    }
                }
            }
            __syncthreads();
        } else {
            __syncthreads();   // protect buf before next-next prefetch
        }
    }

    // raw emission: every thread writes its exact slice-top-8 (no merge stage)
    {
        size_t base = (((size_t)(q0 + qown) * NCHUNKS + blockIdx.y) * PCHUNK) + qtr * 8;
#pragma unroll
        for (int j = 0; j < 8; j++) {
            g_pscore[base + j] = ts[j];
            g_pidx[base + j]   = ti[j];
        }
    }
}

// ---- kernel 4: warp-per-query strided sweep over 4096 entries -> 256 cand ----
__global__ __launch_bounds__(256) void prune_kernel() {
    const int wid = threadIdx.x >> 5, lane = threadIdx.x & 31;
    const int q = blockIdx.x * 8 + wid;
    const float* ps = g_pscore + (size_t)q * NCHUNKS * PCHUNK;
    const int*   pi = g_pidx   + (size_t)q * NCHUNKS * PCHUNK;

    float ts[8]; int ti[8];
#pragma unroll
    for (int j = 0; j < 8; j++) { ts[j] = -INFINITY; ti[j] = 0x7fffffff; }
#pragma unroll 4
    for (int pass = 0; pass < NCHUNKS; pass++) {   // lane sees slot (lane) of each chunk
        int e = pass * PCHUNK + lane;
        float v = ps[e];
        if (v > ts[7]) ins8(ts, ti, v, pi[e]);
    }
    // every lane emits its top-8: 32 x 8 = 256 candidates
#pragma unroll
    for (int j = 0; j < 8; j++)
        g_cand[(size_t)q * NCAND + lane * 8 + j] = ti[j];
}

// ---- kernel 5: exact fp32 rescore of 256 candidates + final top-8 ----
__global__ __launch_bounds__(256) void rescore_kernel(const float* __restrict__ keys,
                                                      float* __restrict__ out_scores) {
    __shared__ float cs[NCAND];
    __shared__ int   ci[NCAND];
    int q = blockIdx.x;
    int wid = threadIdx.x >> 5, lane = threadIdx.x & 31;

    float qv[8];
    *(float4*)&qv[0] = *(const float4*)(g_qn + q * KDIM + lane * 8);
    *(float4*)&qv[4] = *(const float4*)(g_qn + q * KDIM + lane * 8 + 4);

    for (int c = wid; c < NCAND; c += 8) {
        int idx = g_cand[(size_t)q * NCAND + c];
        float kv[8];
        *(float4*)&kv[0] = *(const float4*)(keys + (size_t)idx * KDIM + lane * 8);
        *(float4*)&kv[4] = *(const float4*)(keys + (size_t)idx * KDIM + lane * 8 + 4);
        float ss = 0.f, dt = 0.f;
#pragma unroll
        for (int e = 0; e < 8; e++) { ss += kv[e] * kv[e]; dt += kv[e] * qv[e]; }
#pragma unroll
        for (int o = 16; o > 0; o >>= 1) {
            ss += __shfl_xor_sync(0xffffffffu, ss, o);
            dt += __shfl_xor_sync(0xffffffffu, dt, o);
        }
        if (lane == 0) {
            cs[c] = dt / fmaxf(sqrtf(ss), 1e-12f);
            ci[c] = idx;
        }
    }
    __syncthreads();
    if (threadIdx.x == 0) {
        float ts[TOPK]; int ti[TOPK];
#pragma unroll
        for (int j = 0; j < TOPK; j++) { ts[j] = -INFINITY; ti[j] = 0x7fffffff; }
        for (int c = 0; c < NCAND; c++) {
            float v = cs[c]; int id = ci[c];
            if (better(v, id, ts[TOPK - 1], ti[TOPK - 1])) {
                ts[TOPK - 1] = v; ti[TOPK - 1] = id;
#pragma unroll
                for (int j = TOPK - 1; j > 0; j--) {
                    if (better(ts[j], ti[j], ts[j - 1], ti[j - 1])) {
                        float tf = ts[j]; ts[j] = ts[j - 1]; ts[j - 1] = tf;
                        int   tt = ti[j]; ti[j] = ti[j - 1]; ti[j - 1] = tt;
                    }
                }
            }
        }
#pragma unroll
        for (int j = 0; j < TOPK; j++) {
            out_scores[q * TOPK + j] = ts[j];
            g_topidx[q * TOPK + j]   = ti[j];
        }
    }
}

// ---- kernel 6: gather docs ----
__global__ void gather_kernel(const float* __restrict__ vals, float* __restrict__ out_docs) {
    int b = blockIdx.x;
    int idx = g_topidx[b];
    const float4* src = (const float4*)(vals + (size_t)idx * DMODEL);
    float4* dst = (float4*)(out_docs + (size_t)b * DMODEL);
    dst[threadIdx.x] = src[threadIdx.x];
}

extern "C" void kernel_launch(void* const* d_in, const int* in_sizes, int n_in,
                              void* d_out, int out_size) {
    const float* query = (const float*)d_in[0];
    const float* keys  = (const float*)d_in[1];
    const float* vals  = (const float*)d_in[2];
    float* out        = (float*)d_out;
    float* out_docs   = out;
    float* out_scores = out + (size_t)B_Q * TOPK * DMODEL;

    qnorm_kernel<<<B_Q / 8, 256>>>(query);
    keysprep_kernel<<<NCORP / 8, 256>>>(keys);

    cudaFuncSetAttribute(score_kernel,
                         cudaFuncAttributeMaxDynamicSharedMemorySize, SMEM_TOTAL);
    score_kernel<<<dim3(QTILES, NCHUNKS), 512, SMEM_TOTAL>>>();

    prune_kernel<<<B_Q / 8, 256>>>();
    rescore_kernel<<<B_Q, 256>>>(keys, out_scores);
    gather_kernel<<<B_Q * TOPK, 256>>>(vals, out_docs);
}